// round 1
// baseline (speedup 1.0000x reference)
#include <cuda_runtime.h>

#define N_TOK 2048
#define EDIM  768
#define HEADS 12
#define DH    64

// ------------------------- scratch (no allocs allowed) -------------------------
__device__ float g_x  [N_TOK * EDIM];
__device__ float g_q  [N_TOK * EDIM];
__device__ float g_wqf[EDIM * EDIM];
__device__ float g_zc [EDIM * N_TOK];
__device__ float g_mh [EDIM * N_TOK];
__device__ float g_l1 [N_TOK * EDIM];
__device__ float g_ffn[N_TOK * EDIM];

// ------------------------- positional encoding + add -------------------------
__global__ void add_pe_kernel(const float* __restrict__ tokens, float* __restrict__ x) {
    int idx = blockIdx.x * 256 + threadIdx.x;            // < 2048*768
    int e = idx % EDIM;
    int n = idx / EDIM;
    int s = n & 511;                                     // seq position
    // p = 10000 ^ ((2e)//768)  -> 10000 for e<384, 10001 for e>=384
    float p = (e < 384) ? 10000.0f : 10001.0f;
    float ang = (float)s / p;
    float pe = (e & 1) ? cosf(ang) : sinf(ang);
    x[idx] = tokens[idx] + pe;
}

// WqF[e, h*64+d] = wq_l[h, e, d]
__global__ void make_wqf_kernel(const float* __restrict__ wq_l, float* __restrict__ wqf) {
    int idx = blockIdx.x * 256 + threadIdx.x;            // < 768*768
    int e = idx / EDIM;
    int c = idx % EDIM;
    wqf[idx] = wq_l[(c >> 6) * (EDIM * DH) + e * DH + (c & 63)];
}

// ------------------------- generic SGEMM, 64x64 tile, BK=16 -------------------------
// BMODE 0: B is [K,N] row-major (NN).  BMODE 1: B is [N,K] row-major (NT: C=A*B^T).
template <int BMODE, bool BIAS>
__global__ void sgemm64(const float* __restrict__ A, const float* __restrict__ B,
                        const float* __restrict__ bias, float* __restrict__ C,
                        int M, int N, int K) {
    __shared__ float As[16][68];
    __shared__ float Bs[16][68];
    int tid = threadIdx.x;                // 256 threads
    int tx = tid & 15, ty = tid >> 4;
    int bm = blockIdx.y * 64, bn = blockIdx.x * 64;

    float acc[4][4] = {};

    for (int k0 = 0; k0 < K; k0 += 16) {
        {   // A tile: 64 rows x 16 k, one float4 per thread, store transposed
            int r  = tid >> 2;
            int kc = (tid & 3) << 2;
            float4 v = *(const float4*)&A[(size_t)(bm + r) * K + k0 + kc];
            As[kc + 0][r] = v.x; As[kc + 1][r] = v.y;
            As[kc + 2][r] = v.z; As[kc + 3][r] = v.w;
        }
        if (BMODE == 0) {
            int kr = tid >> 4;
            int nc = (tid & 15) << 2;
            float4 v = *(const float4*)&B[(size_t)(k0 + kr) * N + bn + nc];
            *(float4*)&Bs[kr][nc] = v;
        } else {
            int nr = tid >> 2;
            int kc = (tid & 3) << 2;
            float4 v = *(const float4*)&B[(size_t)(bn + nr) * K + k0 + kc];
            Bs[kc + 0][nr] = v.x; Bs[kc + 1][nr] = v.y;
            Bs[kc + 2][nr] = v.z; Bs[kc + 3][nr] = v.w;
        }
        __syncthreads();
#pragma unroll
        for (int k = 0; k < 16; k++) {
            float4 a = *(const float4*)&As[k][ty * 4];
            float4 b = *(const float4*)&Bs[k][tx * 4];
            float av[4] = {a.x, a.y, a.z, a.w};
            float bv[4] = {b.x, b.y, b.z, b.w};
#pragma unroll
            for (int i = 0; i < 4; i++)
#pragma unroll
                for (int j = 0; j < 4; j++)
                    acc[i][j] += av[i] * bv[j];
        }
        __syncthreads();
    }

    float4 bb = make_float4(0.f, 0.f, 0.f, 0.f);
    if (BIAS) bb = *(const float4*)&bias[bn + tx * 4];
#pragma unroll
    for (int i = 0; i < 4; i++) {
        int row = bm + ty * 4 + i;
        float4 v = make_float4(acc[i][0] + bb.x, acc[i][1] + bb.y,
                               acc[i][2] + bb.z, acc[i][3] + bb.w);
        *(float4*)&C[(size_t)row * N + bn + tx * 4] = v;
    }
}

// ------------------------- flash attention (q == k == v) -------------------------
// grid (32 row-blocks, 12 heads), 256 threads. Output written directly in the
// zc layout: zc[(h*64 + n/32)*2048 + (n%32)*64 + d]  (the reference reshape bug).
#define FLASH_SMEM (50176)
__global__ void flash_attn(const float* __restrict__ Q, float* __restrict__ zc) {
    extern __shared__ float sm[];
    float* Qs = sm;           // 64 x 64
    float* Ps = sm + 4096;    // 64 x 64
    float* Ks = sm + 8192;    // 64 x 68 (padded)
    const int KS = 68;

    int h = blockIdx.y, rb = blockIdx.x;
    int tid = threadIdx.x;
    int tx = tid & 15, ty = tid >> 4;

#pragma unroll
    for (int i = 0; i < 4; i++) {
        int r = ty + i * 16;
        *(float4*)&Qs[r * 64 + tx * 4] =
            *(const float4*)&Q[(size_t)(rb * 64 + r) * EDIM + h * DH + tx * 4];
    }

    float m[4], l[4], O[4][4];
#pragma unroll
    for (int i = 0; i < 4; i++) {
        m[i] = -1e30f; l[i] = 0.f;
#pragma unroll
        for (int j = 0; j < 4; j++) O[i][j] = 0.f;
    }

    for (int ct = 0; ct < 32; ct++) {
        __syncthreads();   // prev iteration done reading Ks
#pragma unroll
        for (int i = 0; i < 4; i++) {
            int r = ty + i * 16;
            *(float4*)&Ks[r * KS + tx * 4] =
                *(const float4*)&Q[(size_t)(ct * 64 + r) * EDIM + h * DH + tx * 4];
        }
        __syncthreads();

        // S = Qb @ Kb^T * 0.125 ; fragment: rows ty*4+i, cols tx+16*j
        float s[4][4] = {};
#pragma unroll 4
        for (int d = 0; d < 64; d += 4) {
            float4 qv[4], kv[4];
#pragma unroll
            for (int i = 0; i < 4; i++) qv[i] = *(const float4*)&Qs[(ty * 4 + i) * 64 + d];
#pragma unroll
            for (int j = 0; j < 4; j++) kv[j] = *(const float4*)&Ks[(tx + 16 * j) * KS + d];
#pragma unroll
            for (int i = 0; i < 4; i++)
#pragma unroll
                for (int j = 0; j < 4; j++)
                    s[i][j] += qv[i].x * kv[j].x + qv[i].y * kv[j].y +
                               qv[i].z * kv[j].z + qv[i].w * kv[j].w;
        }

        float mn[4], ls[4], p[4][4];
#pragma unroll
        for (int i = 0; i < 4; i++) {
            float rm = -1e30f;
#pragma unroll
            for (int j = 0; j < 4; j++) { s[i][j] *= 0.125f; rm = fmaxf(rm, s[i][j]); }
#pragma unroll
            for (int o = 8; o >= 1; o >>= 1) rm = fmaxf(rm, __shfl_xor_sync(0xffffffffu, rm, o));
            mn[i] = fmaxf(m[i], rm);
        }
#pragma unroll
        for (int i = 0; i < 4; i++) {
            float r = 0.f;
#pragma unroll
            for (int j = 0; j < 4; j++) { p[i][j] = __expf(s[i][j] - mn[i]); r += p[i][j]; }
#pragma unroll
            for (int o = 8; o >= 1; o >>= 1) r += __shfl_xor_sync(0xffffffffu, r, o);
            ls[i] = r;
        }
#pragma unroll
        for (int i = 0; i < 4; i++) {
            float a = __expf(m[i] - mn[i]);
            l[i] = l[i] * a + ls[i];
            m[i] = mn[i];
#pragma unroll
            for (int j = 0; j < 4; j++) O[i][j] *= a;
        }
#pragma unroll
        for (int i = 0; i < 4; i++)
#pragma unroll
            for (int j = 0; j < 4; j++)
                Ps[(ty * 4 + i) * 64 + tx + 16 * j] = p[i][j];
        __syncthreads();

        // O += P @ V  (V == K tile) ; O fragment: rows ty*4+i, dims tx*4+j
#pragma unroll 4
        for (int c = 0; c < 64; c += 4) {
            float4 k0 = *(const float4*)&Ks[(c + 0) * KS + tx * 4];
            float4 k1 = *(const float4*)&Ks[(c + 1) * KS + tx * 4];
            float4 k2 = *(const float4*)&Ks[(c + 2) * KS + tx * 4];
            float4 k3 = *(const float4*)&Ks[(c + 3) * KS + tx * 4];
#pragma unroll
            for (int i = 0; i < 4; i++) {
                float4 pp = *(const float4*)&Ps[(ty * 4 + i) * 64 + c];
                O[i][0] += pp.x * k0.x + pp.y * k1.x + pp.z * k2.x + pp.w * k3.x;
                O[i][1] += pp.x * k0.y + pp.y * k1.y + pp.z * k2.y + pp.w * k3.y;
                O[i][2] += pp.x * k0.z + pp.y * k1.z + pp.z * k2.z + pp.w * k3.z;
                O[i][3] += pp.x * k0.w + pp.y * k1.w + pp.z * k2.w + pp.w * k3.w;
            }
        }
    }

#pragma unroll
    for (int i = 0; i < 4; i++) {
        int n = rb * 64 + ty * 4 + i;
        float inv = 1.f / l[i];
        float4 o4 = make_float4(O[i][0] * inv, O[i][1] * inv, O[i][2] * inv, O[i][3] * inv);
        *(float4*)&zc[(size_t)(h * 64 + (n >> 5)) * N_TOK + (n & 31) * 64 + tx * 4] = o4;
    }
}

// ------------------------- fused residual-add + LayerNorm -------------------------
__global__ void add_ln(const float* __restrict__ A, const float* __restrict__ Bd,
                       const float* __restrict__ g, const float* __restrict__ bb,
                       float* __restrict__ out) {
    __shared__ float red[8];
    int n = blockIdx.x, tid = threadIdx.x;     // 256 threads, 768 elems/row
    float loc[3];
    float s = 0.f;
#pragma unroll
    for (int i = 0; i < 3; i++) {
        int e = tid + i * 256;
        float v = A[(size_t)n * EDIM + e] + Bd[(size_t)n * EDIM + e];
        loc[i] = v; s += v;
    }
#pragma unroll
    for (int o = 16; o; o >>= 1) s += __shfl_xor_sync(0xffffffffu, s, o);
    if ((tid & 31) == 0) red[tid >> 5] = s;
    __syncthreads();
    if (tid < 32) {
        float t = (tid < 8) ? red[tid] : 0.f;
#pragma unroll
        for (int o = 4; o; o >>= 1) t += __shfl_xor_sync(0xffffffffu, t, o);
        if (tid == 0) red[0] = t;
    }
    __syncthreads();
    float mu = red[0] * (1.f / 768.f);
    __syncthreads();

    float sq = 0.f;
#pragma unroll
    for (int i = 0; i < 3; i++) { float d = loc[i] - mu; sq += d * d; }
#pragma unroll
    for (int o = 16; o; o >>= 1) sq += __shfl_xor_sync(0xffffffffu, sq, o);
    if ((tid & 31) == 0) red[tid >> 5] = sq;
    __syncthreads();
    if (tid < 32) {
        float t = (tid < 8) ? red[tid] : 0.f;
#pragma unroll
        for (int o = 4; o; o >>= 1) t += __shfl_xor_sync(0xffffffffu, t, o);
        if (tid == 0) red[0] = t;
    }
    __syncthreads();
    float var = red[0] * (1.f / 768.f);
    float inv = rsqrtf(var + 1e-5f);
#pragma unroll
    for (int i = 0; i < 3; i++) {
        int e = tid + i * 256;
        out[(size_t)n * EDIM + e] = (loc[i] - mu) * inv * g[e] + bb[e];
    }
}

// ------------------------- launch -------------------------
extern "C" void kernel_launch(void* const* d_in, const int* in_sizes, int n_in,
                              void* d_out, int out_size) {
    const float* tokens = (const float*)d_in[0];
    const float* wq = (const float*)d_in[1];
    const float* wo = (const float*)d_in[2];
    const float* g1 = (const float*)d_in[3];
    const float* b1 = (const float*)d_in[4];
    const float* fw = (const float*)d_in[5];
    const float* fb = (const float*)d_in[6];
    const float* g2 = (const float*)d_in[7];
    const float* b2 = (const float*)d_in[8];
    float* out = (float*)d_out;

    float *x, *q, *wqf, *zc, *mh, *l1, *ffn;
    cudaGetSymbolAddress((void**)&x,   g_x);
    cudaGetSymbolAddress((void**)&q,   g_q);
    cudaGetSymbolAddress((void**)&wqf, g_wqf);
    cudaGetSymbolAddress((void**)&zc,  g_zc);
    cudaGetSymbolAddress((void**)&mh,  g_mh);
    cudaGetSymbolAddress((void**)&l1,  g_l1);
    cudaGetSymbolAddress((void**)&ffn, g_ffn);

    cudaFuncSetAttribute(flash_attn, cudaFuncAttributeMaxDynamicSharedMemorySize, FLASH_SMEM);

    add_pe_kernel<<<(N_TOK * EDIM) / 256, 256>>>(tokens, x);

    for (int step = 0; step < 13; step++) {
        int lidx = (step == 0) ? 0 : step - 1;
        const float* wq_l = wq + (size_t)lidx * EDIM * EDIM;   // H*E*D = 768*768
        const float* wo_l = wo + (size_t)lidx * EDIM * EDIM;
        const float* fw_l = fw + (size_t)lidx * EDIM * EDIM;
        const float* g1_l = g1 + lidx * EDIM;
        const float* b1_l = b1 + lidx * EDIM;
        const float* fb_l = fb + lidx * EDIM;
        const float* g2_l = g2 + lidx * EDIM;
        const float* b2_l = b2 + lidx * EDIM;

        // Q = X @ WqF         [2048,768] x [768,768]
        make_wqf_kernel<<<(EDIM * EDIM) / 256, 256>>>(wq_l, wqf);
        sgemm64<0, false><<<dim3(EDIM / 64, N_TOK / 64), 256>>>(x, wqf, nullptr, q,
                                                                N_TOK, EDIM, EDIM);
        // attention -> zc (scrambled layout, written directly)
        flash_attn<<<dim3(32, HEADS), 256, FLASH_SMEM>>>(q, zc);

        // mh = Wo @ zc        [768,768] x [768,2048]; flat buffer == reshaped [B,S,E]
        sgemm64<0, false><<<dim3(N_TOK / 64, EDIM / 64), 256>>>(wo_l, zc, nullptr, mh,
                                                                EDIM, N_TOK, EDIM);
        // l1 = LN(x + mh)
        add_ln<<<N_TOK, 256>>>(x, mh, g1_l, b1_l, l1);

        // ffn = l1 @ fw^T + fb
        sgemm64<1, true><<<dim3(EDIM / 64, N_TOK / 64), 256>>>(l1, fw_l, fb_l, ffn,
                                                               N_TOK, EDIM, EDIM);
        // x = LN(l1 + ffn)   (last layer writes d_out)
        add_ln<<<N_TOK, 256>>>(l1, ffn, g2_l, b2_l, (step == 12) ? out : x);
    }
}

// round 4
// speedup vs baseline: 2.3263x; 2.3263x over previous
#include <cuda_runtime.h>
#include <cuda_bf16.h>
#include <mma.h>
#include <cstdint>

using namespace nvcuda;

#define N_TOK 2048
#define EDIM  768
#define HEADS 12
#define DH    64

__device__ float g_x   [N_TOK * EDIM];
__device__ float g_q   [N_TOK * EDIM];
__device__ float g_wqfT[EDIM * EDIM];
__device__ float g_zc  [EDIM * N_TOK];
__device__ float g_zcT [N_TOK * EDIM];
__device__ float g_mh  [EDIM * N_TOK];
__device__ float g_l1  [N_TOK * EDIM];
__device__ float g_ffn [N_TOK * EDIM];

__device__ __forceinline__ uint32_t smem_u32(const void* p) {
    uint32_t a;
    asm("{ .reg .u64 t; cvta.to.shared.u64 t, %1; cvt.u32.u64 %0, t; }" : "=r"(a) : "l"(p));
    return a;
}
__device__ __forceinline__ uint32_t pk2(float lo, float hi) {
    uint32_t r;
    asm("cvt.rn.bf16x2.f32 %0, %1, %2;" : "=r"(r) : "f"(hi), "f"(lo));
    return r;
}
__device__ __forceinline__ void cvt_hl(float2 v, __nv_bfloat16* hid, __nv_bfloat16* lod) {
    __nv_bfloat16 h0 = __float2bfloat16(v.x), h1 = __float2bfloat16(v.y);
    __nv_bfloat162 hp; hp.x = h0; hp.y = h1;
    *(__nv_bfloat162*)hid = hp;
    __nv_bfloat162 lp;
    lp.x = __float2bfloat16(v.x - __bfloat162float(h0));
    lp.y = __float2bfloat16(v.y - __bfloat162float(h1));
    *(__nv_bfloat162*)lod = lp;
}
__device__ __forceinline__ void mma16816(float* c, const uint32_t* a, uint32_t b0, uint32_t b1) {
    asm volatile("mma.sync.aligned.m16n8k16.row.col.f32.bf16.bf16.f32 "
                 "{%0,%1,%2,%3}, {%4,%5,%6,%7}, {%8,%9}, {%0,%1,%2,%3};"
                 : "+f"(c[0]), "+f"(c[1]), "+f"(c[2]), "+f"(c[3])
                 : "r"(a[0]), "r"(a[1]), "r"(a[2]), "r"(a[3]), "r"(b0), "r"(b1));
}
__device__ __forceinline__ void ldm4(uint32_t* r, uint32_t addr) {
    asm volatile("ldmatrix.sync.aligned.m8n8.x4.shared.b16 {%0,%1,%2,%3}, [%4];"
                 : "=r"(r[0]), "=r"(r[1]), "=r"(r[2]), "=r"(r[3]) : "r"(addr));
}
__device__ __forceinline__ void ldm4t(uint32_t* r, uint32_t addr) {
    asm volatile("ldmatrix.sync.aligned.m8n8.x4.trans.shared.b16 {%0,%1,%2,%3}, [%4];"
                 : "=r"(r[0]), "=r"(r[1]), "=r"(r[2]), "=r"(r[3]) : "r"(addr));
}

// ---------------- wmma split-bf16 GEMM: D[M,N] = A[M,K] * B[N,K]^T ----------------
#define GLD 72
#define GEMM_SMEM (4 * 128 * GLD * 2)

__global__ void __launch_bounds__(256)
gemm_wmma(const float* __restrict__ A, const float* __restrict__ B,
          float* __restrict__ C, int M, int N, int K) {
    extern __shared__ __nv_bfloat16 sm[];
    __nv_bfloat16* Ah = sm;
    __nv_bfloat16* Al = sm + 128 * GLD;
    __nv_bfloat16* Bh = sm + 2 * 128 * GLD;
    __nv_bfloat16* Bl = sm + 3 * 128 * GLD;

    int tid = threadIdx.x, wid = tid >> 5;
    int bm = blockIdx.y * 128, bn = blockIdx.x * 128;
    int wm = (wid >> 1) * 32, wn = (wid & 1) * 64;

    wmma::fragment<wmma::accumulator, 16, 16, 16, float> acc[2][4];
#pragma unroll
    for (int i = 0; i < 2; i++)
#pragma unroll
        for (int j = 0; j < 4; j++) wmma::fill_fragment(acc[i][j], 0.f);

    for (int k0 = 0; k0 < K; k0 += 64) {
        __syncthreads();
#pragma unroll
        for (int i = 0; i < 16; i++) {
            int idx = tid + 256 * i;
            int r = idx >> 5, c2 = (idx & 31) * 2;
            float2 va = *(const float2*)&A[(size_t)(bm + r) * K + k0 + c2];
            cvt_hl(va, &Ah[r * GLD + c2], &Al[r * GLD + c2]);
            float2 vb = *(const float2*)&B[(size_t)(bn + r) * K + k0 + c2];
            cvt_hl(vb, &Bh[r * GLD + c2], &Bl[r * GLD + c2]);
        }
        __syncthreads();

#pragma unroll
        for (int kc = 0; kc < 4; kc++) {
            wmma::fragment<wmma::matrix_a, 16, 16, 16, __nv_bfloat16, wmma::row_major> ah[2], al[2];
#pragma unroll
            for (int i = 0; i < 2; i++) {
                wmma::load_matrix_sync(ah[i], &Ah[(wm + 16 * i) * GLD + kc * 16], GLD);
                wmma::load_matrix_sync(al[i], &Al[(wm + 16 * i) * GLD + kc * 16], GLD);
            }
#pragma unroll
            for (int j = 0; j < 4; j++) {
                wmma::fragment<wmma::matrix_b, 16, 16, 16, __nv_bfloat16, wmma::col_major> bh, bl;
                wmma::load_matrix_sync(bh, &Bh[(wn + 16 * j) * GLD + kc * 16], GLD);
                wmma::load_matrix_sync(bl, &Bl[(wn + 16 * j) * GLD + kc * 16], GLD);
#pragma unroll
                for (int i = 0; i < 2; i++) {
                    wmma::mma_sync(acc[i][j], ah[i], bh, acc[i][j]);
                    wmma::mma_sync(acc[i][j], ah[i], bl, acc[i][j]);
                    wmma::mma_sync(acc[i][j], al[i], bh, acc[i][j]);
                }
            }
        }
    }
#pragma unroll
    for (int i = 0; i < 2; i++)
#pragma unroll
        for (int j = 0; j < 4; j++)
            wmma::store_matrix_sync(&C[(size_t)(bm + wm + 16 * i) * N + bn + wn + 16 * j],
                                    acc[i][j], N, wmma::mem_row_major);
}

// ---------------- flash attention, mma.sync split-bf16 (q==k==v) ----------------
#define FLD 72
__global__ void __launch_bounds__(128, 3)
flash_mma(const float* __restrict__ Q, float* __restrict__ zc) {
    __shared__ __nv_bfloat16 sQ[2][64 * FLD];
    __shared__ __nv_bfloat16 sK[2][64 * FLD];

    int tid = threadIdx.x, lane = tid & 31, wid = tid >> 5;
    int h = blockIdx.y, rb = blockIdx.x;

#pragma unroll
    for (int i = 0; i < 16; i++) {
        int idx = tid + 128 * i;
        int r = idx >> 5, c2 = (idx & 31) * 2;
        float2 v = *(const float2*)&Q[(size_t)(rb * 64 + r) * EDIM + h * DH + c2];
        cvt_hl(v, &sQ[0][r * FLD + c2], &sQ[1][r * FLD + c2]);
    }
    __syncthreads();

    int ar = wid * 16 + (lane >> 2);
    int ac = 2 * (lane & 3);
    uint32_t qah[4][4], qal[4][4];
#pragma unroll
    for (int kc = 0; kc < 4; kc++) {
        int cb = kc * 16 + ac;
        qah[kc][0] = *(uint32_t*)&sQ[0][(ar)     * FLD + cb];
        qah[kc][1] = *(uint32_t*)&sQ[0][(ar + 8) * FLD + cb];
        qah[kc][2] = *(uint32_t*)&sQ[0][(ar)     * FLD + cb + 8];
        qah[kc][3] = *(uint32_t*)&sQ[0][(ar + 8) * FLD + cb + 8];
        qal[kc][0] = *(uint32_t*)&sQ[1][(ar)     * FLD + cb];
        qal[kc][1] = *(uint32_t*)&sQ[1][(ar + 8) * FLD + cb];
        qal[kc][2] = *(uint32_t*)&sQ[1][(ar)     * FLD + cb + 8];
        qal[kc][3] = *(uint32_t*)&sQ[1][(ar + 8) * FLD + cb + 8];
    }

    float m0 = -1e30f, m1 = -1e30f, l0 = 0.f, l1 = 0.f;
    float o[8][4];
#pragma unroll
    for (int j = 0; j < 8; j++)
#pragma unroll
        for (int c = 0; c < 4; c++) o[j][c] = 0.f;

    uint32_t khb = smem_u32(sK[0]), klb = smem_u32(sK[1]);
    int g = lane >> 3, i8 = lane & 7;
    uint32_t offS = (uint32_t)(((g >> 1) * 8 + i8) * FLD + (g & 1) * 8) * 2;
    uint32_t offV = (uint32_t)(((g & 1) * 8 + i8) * FLD + (g >> 1) * 8) * 2;

    for (int ct = 0; ct < 32; ct++) {
        float2 kv[16];
#pragma unroll
        for (int i = 0; i < 16; i++) {
            int idx = tid + 128 * i;
            int r = idx >> 5, c2 = (idx & 31) * 2;
            kv[i] = *(const float2*)&Q[(size_t)(ct * 64 + r) * EDIM + h * DH + c2];
        }
        __syncthreads();
#pragma unroll
        for (int i = 0; i < 16; i++) {
            int idx = tid + 128 * i;
            int r = idx >> 5, c2 = (idx & 31) * 2;
            cvt_hl(kv[i], &sK[0][r * FLD + c2], &sK[1][r * FLD + c2]);
        }
        __syncthreads();

        float sacc[8][4];
#pragma unroll
        for (int j = 0; j < 8; j++)
#pragma unroll
            for (int c = 0; c < 4; c++) sacc[j][c] = 0.f;
#pragma unroll
        for (int kc = 0; kc < 4; kc++) {
#pragma unroll
            for (int jp = 0; jp < 4; jp++) {
                uint32_t toff = (uint32_t)(jp * 16 * FLD + kc * 16) * 2;
                uint32_t bh[4], bl[4];
                ldm4(bh, khb + offS + toff);
                ldm4(bl, klb + offS + toff);
                mma16816(sacc[2 * jp],     qah[kc], bh[0], bh[1]);
                mma16816(sacc[2 * jp],     qah[kc], bl[0], bl[1]);
                mma16816(sacc[2 * jp],     qal[kc], bh[0], bh[1]);
                mma16816(sacc[2 * jp + 1], qah[kc], bh[2], bh[3]);
                mma16816(sacc[2 * jp + 1], qah[kc], bl[2], bl[3]);
                mma16816(sacc[2 * jp + 1], qal[kc], bh[2], bh[3]);
            }
        }

        float mx0 = -1e30f, mx1 = -1e30f;
#pragma unroll
        for (int j = 0; j < 8; j++) {
#pragma unroll
            for (int c = 0; c < 4; c++) sacc[j][c] *= 0.125f;
            mx0 = fmaxf(mx0, fmaxf(sacc[j][0], sacc[j][1]));
            mx1 = fmaxf(mx1, fmaxf(sacc[j][2], sacc[j][3]));
        }
        mx0 = fmaxf(mx0, __shfl_xor_sync(0xffffffffu, mx0, 1));
        mx0 = fmaxf(mx0, __shfl_xor_sync(0xffffffffu, mx0, 2));
        mx1 = fmaxf(mx1, __shfl_xor_sync(0xffffffffu, mx1, 1));
        mx1 = fmaxf(mx1, __shfl_xor_sync(0xffffffffu, mx1, 2));
        float mn0 = fmaxf(m0, mx0), mn1 = fmaxf(m1, mx1);
        float al0 = __expf(m0 - mn0), al1 = __expf(m1 - mn1);

        float rs0 = 0.f, rs1 = 0.f;
        uint32_t pah[4][4], pal[4][4];
#pragma unroll
        for (int j = 0; j < 8; j++) {
            float p0 = __expf(sacc[j][0] - mn0);
            float p1 = __expf(sacc[j][1] - mn0);
            float p2 = __expf(sacc[j][2] - mn1);
            float p3 = __expf(sacc[j][3] - mn1);
            rs0 += p0 + p1; rs1 += p2 + p3;
            float f0 = __bfloat162float(__float2bfloat16(p0));
            float f1 = __bfloat162float(__float2bfloat16(p1));
            float f2 = __bfloat162float(__float2bfloat16(p2));
            float f3 = __bfloat162float(__float2bfloat16(p3));
            int kc = j >> 1, off = (j & 1) * 2;
            pah[kc][off]     = pk2(p0, p1);
            pah[kc][off + 1] = pk2(p2, p3);
            pal[kc][off]     = pk2(p0 - f0, p1 - f1);
            pal[kc][off + 1] = pk2(p2 - f2, p3 - f3);
        }
        rs0 += __shfl_xor_sync(0xffffffffu, rs0, 1);
        rs0 += __shfl_xor_sync(0xffffffffu, rs0, 2);
        rs1 += __shfl_xor_sync(0xffffffffu, rs1, 1);
        rs1 += __shfl_xor_sync(0xffffffffu, rs1, 2);
        l0 = l0 * al0 + rs0;
        l1 = l1 * al1 + rs1;
        m0 = mn0; m1 = mn1;
#pragma unroll
        for (int j = 0; j < 8; j++) {
            o[j][0] *= al0; o[j][1] *= al0;
            o[j][2] *= al1; o[j][3] *= al1;
        }

#pragma unroll
        for (int kc = 0; kc < 4; kc++) {
#pragma unroll
            for (int jdp = 0; jdp < 4; jdp++) {
                uint32_t toff = (uint32_t)(kc * 16 * FLD + jdp * 16) * 2;
                uint32_t vh[4], vl[4];
                ldm4t(vh, khb + offV + toff);
                ldm4t(vl, klb + offV + toff);
                mma16816(o[2 * jdp],     pah[kc], vh[0], vh[1]);
                mma16816(o[2 * jdp],     pah[kc], vl[0], vl[1]);
                mma16816(o[2 * jdp],     pal[kc], vh[0], vh[1]);
                mma16816(o[2 * jdp + 1], pah[kc], vh[2], vh[3]);
                mma16816(o[2 * jdp + 1], pah[kc], vl[2], vl[3]);
                mma16816(o[2 * jdp + 1], pal[kc], vh[2], vh[3]);
            }
        }
    }

    float inv0 = 1.f / l0, inv1 = 1.f / l1;
    int n0 = rb * 64 + ar, n1 = n0 + 8;
#pragma unroll
    for (int jd = 0; jd < 8; jd++) {
        int d = jd * 8 + ac;
        float2 v0 = make_float2(o[jd][0] * inv0, o[jd][1] * inv0);
        *(float2*)&zc[(size_t)(h * 64 + (n0 >> 5)) * N_TOK + (n0 & 31) * 64 + d] = v0;
        float2 v1 = make_float2(o[jd][2] * inv1, o[jd][3] * inv1);
        *(float2*)&zc[(size_t)(h * 64 + (n1 >> 5)) * N_TOK + (n1 & 31) * 64 + d] = v1;
    }
}

// ---------------- misc small kernels ----------------
__global__ void add_pe_kernel(const float* __restrict__ tokens, float* __restrict__ x) {
    int idx = blockIdx.x * 256 + threadIdx.x;
    int e = idx % EDIM;
    int n = idx / EDIM;
    int s = n & 511;
    float p = (e < 384) ? 10000.0f : 10001.0f;
    float ang = (float)s / p;
    float pe = (e & 1) ? cosf(ang) : sinf(ang);
    x[idx] = tokens[idx] + pe;
}

__global__ void make_wqfT_kernel(const float* __restrict__ wq_l, float* __restrict__ wqfT) {
    int idx = blockIdx.x * 256 + threadIdx.x;
    int n = idx / EDIM;
    int e = idx % EDIM;
    wqfT[idx] = wq_l[(n >> 6) * (EDIM * DH) + e * DH + (n & 63)];
}

__global__ void transpose_zc(const float* __restrict__ in, float* __restrict__ out) {
    __shared__ float t[32][33];
    int bx = blockIdx.x * 32;
    int by = blockIdx.y * 32;
    int x = threadIdx.x, y = threadIdx.y;
#pragma unroll
    for (int i = 0; i < 32; i += 8)
        t[y + i][x] = in[(size_t)(by + y + i) * N_TOK + bx + x];
    __syncthreads();
#pragma unroll
    for (int i = 0; i < 32; i += 8)
        out[(size_t)(bx + y + i) * EDIM + by + x] = t[x][y + i];
}

__global__ void add_ln(const float* __restrict__ A, const float* __restrict__ Bd,
                       const float* __restrict__ g, const float* __restrict__ bb,
                       const float* __restrict__ extra, float* __restrict__ out) {
    __shared__ float red[8];
    int n = blockIdx.x, tid = threadIdx.x;
    float loc[3];
    float s = 0.f;
#pragma unroll
    for (int i = 0; i < 3; i++) {
        int e = tid + i * 256;
        float v = A[(size_t)n * EDIM + e] + Bd[(size_t)n * EDIM + e];
        if (extra) v += extra[e];
        loc[i] = v; s += v;
    }
#pragma unroll
    for (int o = 16; o; o >>= 1) s += __shfl_xor_sync(0xffffffffu, s, o);
    if ((tid & 31) == 0) red[tid >> 5] = s;
    __syncthreads();
    if (tid < 32) {
        float t = (tid < 8) ? red[tid] : 0.f;
#pragma unroll
        for (int o = 4; o; o >>= 1) t += __shfl_xor_sync(0xffffffffu, t, o);
        if (tid == 0) red[0] = t;
    }
    __syncthreads();
    float mu = red[0] * (1.f / 768.f);
    __syncthreads();

    float sq = 0.f;
#pragma unroll
    for (int i = 0; i < 3; i++) { float d = loc[i] - mu; sq += d * d; }
#pragma unroll
    for (int o = 16; o; o >>= 1) sq += __shfl_xor_sync(0xffffffffu, sq, o);
    if ((tid & 31) == 0) red[tid >> 5] = sq;
    __syncthreads();
    if (tid < 32) {
        float t = (tid < 8) ? red[tid] : 0.f;
#pragma unroll
        for (int o = 4; o; o >>= 1) t += __shfl_xor_sync(0xffffffffu, t, o);
        if (tid == 0) red[0] = t;
    }
    __syncthreads();
    float var = red[0] * (1.f / 768.f);
    float inv = rsqrtf(var + 1e-5f);
#pragma unroll
    for (int i = 0; i < 3; i++) {
        int e = tid + i * 256;
        out[(size_t)n * EDIM + e] = (loc[i] - mu) * inv * g[e] + bb[e];
    }
}

// ---------------- launch ----------------
extern "C" void kernel_launch(void* const* d_in, const int* in_sizes, int n_in,
                              void* d_out, int out_size) {
    const float* tokens = (const float*)d_in[0];
    const float* wq = (const float*)d_in[1];
    const float* wo = (const float*)d_in[2];
    const float* g1 = (const float*)d_in[3];
    const float* b1 = (const float*)d_in[4];
    const float* fw = (const float*)d_in[5];
    const float* fb = (const float*)d_in[6];
    const float* g2 = (const float*)d_in[7];
    const float* b2 = (const float*)d_in[8];
    float* out = (float*)d_out;

    float *x, *q, *wqfT, *zc, *zcT, *mh, *l1, *ffn;
    cudaGetSymbolAddress((void**)&x,    g_x);
    cudaGetSymbolAddress((void**)&q,    g_q);
    cudaGetSymbolAddress((void**)&wqfT, g_wqfT);
    cudaGetSymbolAddress((void**)&zc,   g_zc);
    cudaGetSymbolAddress((void**)&zcT,  g_zcT);
    cudaGetSymbolAddress((void**)&mh,   g_mh);
    cudaGetSymbolAddress((void**)&l1,   g_l1);
    cudaGetSymbolAddress((void**)&ffn,  g_ffn);

    cudaFuncSetAttribute(gemm_wmma, cudaFuncAttributeMaxDynamicSharedMemorySize, GEMM_SMEM);

    add_pe_kernel<<<(N_TOK * EDIM) / 256, 256>>>(tokens, x);

    for (int step = 0; step < 13; step++) {
        int lidx = (step == 0) ? 0 : step - 1;
        const float* wq_l = wq + (size_t)lidx * EDIM * EDIM;
        const float* wo_l = wo + (size_t)lidx * EDIM * EDIM;
        const float* fw_l = fw + (size_t)lidx * EDIM * EDIM;
        const float* g1_l = g1 + lidx * EDIM;
        const float* b1_l = b1 + lidx * EDIM;
        const float* fb_l = fb + lidx * EDIM;
        const float* g2_l = g2 + lidx * EDIM;
        const float* b2_l = b2 + lidx * EDIM;

        make_wqfT_kernel<<<(EDIM * EDIM) / 256, 256>>>(wq_l, wqfT);
        gemm_wmma<<<dim3(EDIM / 128, N_TOK / 128), 256, GEMM_SMEM>>>(
            x, wqfT, q, N_TOK, EDIM, EDIM);

        flash_mma<<<dim3(32, HEADS), 128>>>(q, zc);

        transpose_zc<<<dim3(N_TOK / 32, EDIM / 32), dim3(32, 8)>>>(zc, zcT);
        gemm_wmma<<<dim3(N_TOK / 128, EDIM / 128), 256, GEMM_SMEM>>>(
            wo_l, zcT, mh, EDIM, N_TOK, EDIM);

        add_ln<<<N_TOK, 256>>>(x, mh, g1_l, b1_l, nullptr, l1);

        gemm_wmma<<<dim3(EDIM / 128, N_TOK / 128), 256, GEMM_SMEM>>>(
            l1, fw_l, ffn, N_TOK, EDIM, EDIM);

        add_ln<<<N_TOK, 256>>>(l1, ffn, g2_l, b2_l, fb_l, (step == 12) ? out : x);
    }
}